// round 1
// baseline (speedup 1.0000x reference)
#include <cuda_runtime.h>
#include <math.h>

#define NN 4096
#define MM 4096
#define DD 64
#define W_EPS 0.1f
#define INV_EPS 10.0f
#define ITERS 10
#define ROWS_PER_SLAB 128
#define SLABS (NN / ROWS_PER_SLAB)   // 32

// ---------------- device scratch (static globals; no allocations) ----------------
__device__ __align__(16) float d_C[(size_t)NN * MM];   // 64 MB cost matrix
__device__ __align__(16) float d_f[NN];
__device__ __align__(16) float d_g[MM];
__device__ __align__(16) float d_nx[NN];
__device__ __align__(16) float d_ny[MM];
__device__ __align__(16) float d_pm[SLABS * MM];       // column-pass partial max
__device__ __align__(16) float d_ps[SLABS * MM];       // column-pass partial sum
__device__ double d_parts[16384];                      // cost partials (deterministic)

// ---------------- init: zero g ----------------
__global__ void k_init() {
    int i = blockIdx.x * 256 + threadIdx.x;
    if (i < MM) d_g[i] = 0.0f;
}

// ---------------- row norms: warp per row ----------------
__global__ void k_norms(const float* __restrict__ x, int sel) {
    int row = blockIdx.x * 8 + (threadIdx.x >> 5);
    int lane = threadIdx.x & 31;
    float a = x[row * DD + lane];
    float b = x[row * DD + 32 + lane];
    float s = a * a + b * b;
    #pragma unroll
    for (int o = 16; o; o >>= 1) s += __shfl_xor_sync(0xffffffffu, s, o);
    if (lane == 0) {
        if (sel) d_ny[row] = s; else d_nx[row] = s;
    }
}

// ---------------- C = nx_i + ny_j - 2 x.y : 64x64 tile, 4x4 micro ----------------
__global__ void k_cost(const float* __restrict__ x, const float* __restrict__ y) {
    __shared__ float xs[DD][65];   // transposed: xs[d][row], pitch 65 (odd -> bank stride 1)
    __shared__ float ys[DD][65];
    int t = threadIdx.x;
    int tx = t & 15, ty = t >> 4;
    int rowBase = blockIdx.y * 64, colBase = blockIdx.x * 64;

    #pragma unroll
    for (int k = 0; k < 4; k++) {
        int idx = t + 256 * k;          // 0..1023
        int r  = idx >> 4;              // 0..63
        int dv = (idx & 15) << 2;       // 0..60
        float4 v = *(const float4*)(x + (size_t)(rowBase + r) * DD + dv);
        xs[dv + 0][r] = v.x; xs[dv + 1][r] = v.y; xs[dv + 2][r] = v.z; xs[dv + 3][r] = v.w;
        float4 w = *(const float4*)(y + (size_t)(colBase + r) * DD + dv);
        ys[dv + 0][r] = w.x; ys[dv + 1][r] = w.y; ys[dv + 2][r] = w.z; ys[dv + 3][r] = w.w;
    }
    __syncthreads();

    float acc[4][4] = {};
    #pragma unroll 8
    for (int d = 0; d < DD; d++) {
        float a0 = xs[d][ty * 4 + 0], a1 = xs[d][ty * 4 + 1];
        float a2 = xs[d][ty * 4 + 2], a3 = xs[d][ty * 4 + 3];
        float b0 = ys[d][tx * 4 + 0], b1 = ys[d][tx * 4 + 1];
        float b2 = ys[d][tx * 4 + 2], b3 = ys[d][tx * 4 + 3];
        acc[0][0] = fmaf(a0, b0, acc[0][0]); acc[0][1] = fmaf(a0, b1, acc[0][1]);
        acc[0][2] = fmaf(a0, b2, acc[0][2]); acc[0][3] = fmaf(a0, b3, acc[0][3]);
        acc[1][0] = fmaf(a1, b0, acc[1][0]); acc[1][1] = fmaf(a1, b1, acc[1][1]);
        acc[1][2] = fmaf(a1, b2, acc[1][2]); acc[1][3] = fmaf(a1, b3, acc[1][3]);
        acc[2][0] = fmaf(a2, b0, acc[2][0]); acc[2][1] = fmaf(a2, b1, acc[2][1]);
        acc[2][2] = fmaf(a2, b2, acc[2][2]); acc[2][3] = fmaf(a2, b3, acc[2][3]);
        acc[3][0] = fmaf(a3, b0, acc[3][0]); acc[3][1] = fmaf(a3, b1, acc[3][1]);
        acc[3][2] = fmaf(a3, b2, acc[3][2]); acc[3][3] = fmaf(a3, b3, acc[3][3]);
    }

    float4 nyv = *(const float4*)(d_ny + colBase + tx * 4);
    #pragma unroll
    for (int r = 0; r < 4; r++) {
        float nxr = d_nx[rowBase + ty * 4 + r];
        float4 o;
        o.x = nxr + nyv.x - 2.0f * acc[r][0];
        o.y = nxr + nyv.y - 2.0f * acc[r][1];
        o.z = nxr + nyv.z - 2.0f * acc[r][2];
        o.w = nxr + nyv.w - 2.0f * acc[r][3];
        *(float4*)(d_C + (size_t)(rowBase + ty * 4 + r) * MM + colBase + tx * 4) = o;
    }
}

// ---------------- block reductions (broadcast result) ----------------
__device__ __forceinline__ float blockMax(float v, float* red) {
    #pragma unroll
    for (int o = 16; o; o >>= 1) v = fmaxf(v, __shfl_xor_sync(0xffffffffu, v, o));
    if ((threadIdx.x & 31) == 0) red[threadIdx.x >> 5] = v;
    __syncthreads();
    if (threadIdx.x == 0) {
        float m = red[0];
        #pragma unroll
        for (int k = 1; k < 8; k++) m = fmaxf(m, red[k]);
        red[8] = m;
    }
    __syncthreads();
    return red[8];
}

__device__ __forceinline__ float blockSum(float v, float* red) {
    #pragma unroll
    for (int o = 16; o; o >>= 1) v += __shfl_xor_sync(0xffffffffu, v, o);
    if ((threadIdx.x & 31) == 0) red[threadIdx.x >> 5] = v;
    __syncthreads();
    if (threadIdx.x == 0) {
        float m = red[0];
        #pragma unroll
        for (int k = 1; k < 8; k++) m += red[k];
        red[8] = m;
    }
    __syncthreads();
    return red[8];
}

// ---------------- row pass: f_i = eps*(logp_i - LSE_j((g_j - C_ij)/eps)) ----------------
// 4 rows per block to amortize staging g into shared.
__global__ void k_row(const float* __restrict__ p) {
    __shared__ __align__(16) float gs[MM];
    __shared__ float red[9];
    int t = threadIdx.x;
    #pragma unroll
    for (int k = 0; k < 4; k++) {
        int j = (t + 256 * k) * 4;
        *(float4*)(gs + j) = *(const float4*)(d_g + j);
    }
    __syncthreads();

    int rowBase = blockIdx.x * 4;
    for (int rr = 0; rr < 4; rr++) {
        int i = rowBase + rr;
        const float* Crow = d_C + (size_t)i * MM;
        float v[16];
        float mx = -INFINITY;
        #pragma unroll
        for (int k = 0; k < 4; k++) {
            int j = (t + 256 * k) * 4;
            float4 c4 = *(const float4*)(Crow + j);
            float4 g4 = *(const float4*)(gs + j);
            v[4 * k + 0] = (g4.x - c4.x) * INV_EPS;
            v[4 * k + 1] = (g4.y - c4.y) * INV_EPS;
            v[4 * k + 2] = (g4.z - c4.z) * INV_EPS;
            v[4 * k + 3] = (g4.w - c4.w) * INV_EPS;
            mx = fmaxf(mx, fmaxf(fmaxf(v[4 * k + 0], v[4 * k + 1]),
                                 fmaxf(v[4 * k + 2], v[4 * k + 3])));
        }
        mx = blockMax(mx, red);
        float s = 0.0f;
        #pragma unroll
        for (int k = 0; k < 16; k++) s += __expf(v[k] - mx);
        s = blockSum(s, red);
        if (t == 0) d_f[i] = W_EPS * (logf(p[i]) - mx - logf(s));
        __syncthreads();
    }
}

// ---------------- column pass partials: online LSE over a 128-row slab ----------------
__global__ void k_colpart() {
    __shared__ float fs[ROWS_PER_SLAB];
    int t = threadIdx.x;
    int slab = blockIdx.y;
    int col = blockIdx.x * 256 + t;
    if (t < ROWS_PER_SLAB) fs[t] = d_f[slab * ROWS_PER_SLAB + t];
    __syncthreads();

    const float* Cp = d_C + (size_t)slab * ROWS_PER_SLAB * MM + col;
    float m = (fs[0] - Cp[0]) * INV_EPS;
    float s = 1.0f;
    #pragma unroll 4
    for (int r = 1; r < ROWS_PER_SLAB; r++) {
        float v = (fs[r] - Cp[(size_t)r * MM]) * INV_EPS;
        if (v <= m) {
            s += __expf(v - m);
        } else {
            s = s * __expf(m - v) + 1.0f;
            m = v;
        }
    }
    d_pm[slab * MM + col] = m;
    d_ps[slab * MM + col] = s;
}

// ---------------- column pass combine: g_j = eps*(logq_j - LSE) ----------------
__global__ void k_colfin(const float* __restrict__ q) {
    int j = blockIdx.x * 256 + threadIdx.x;
    float m = d_pm[j], s = d_ps[j];
    #pragma unroll 4
    for (int k = 1; k < SLABS; k++) {
        float mk = d_pm[k * MM + j], sk = d_ps[k * MM + j];
        if (mk <= m) {
            s += sk * __expf(mk - m);
        } else {
            s = s * __expf(m - mk) + sk;
            m = mk;
        }
    }
    d_g[j] = W_EPS * (logf(q[j]) - m - logf(s));
}

// ---------------- final: P = exp((f+g-C)/eps), cost partials ----------------
__global__ void k_final(float* __restrict__ Pout, int writeP) {
    __shared__ float red[8];
    int tid = blockIdx.x * 256 + threadIdx.x;
    int base = tid * 4;
    int i = base >> 12;          // /4096
    int j = base & (MM - 1);
    float4 c4 = *(const float4*)(d_C + (size_t)base);
    float fi = d_f[i];
    float4 g4 = *(const float4*)(d_g + j);
    float p0 = __expf((fi + g4.x - c4.x) * INV_EPS);
    float p1 = __expf((fi + g4.y - c4.y) * INV_EPS);
    float p2 = __expf((fi + g4.z - c4.z) * INV_EPS);
    float p3 = __expf((fi + g4.w - c4.w) * INV_EPS);
    if (writeP) {   // Pout may be 4-byte aligned only (out+1) -> scalar stores
        Pout[base + 0] = p0; Pout[base + 1] = p1;
        Pout[base + 2] = p2; Pout[base + 3] = p3;
    }
    float local = p0 * c4.x + p1 * c4.y + p2 * c4.z + p3 * c4.w;
    #pragma unroll
    for (int o = 16; o; o >>= 1) local += __shfl_xor_sync(0xffffffffu, local, o);
    if ((threadIdx.x & 31) == 0) red[threadIdx.x >> 5] = local;
    __syncthreads();
    if (threadIdx.x == 0) {
        double s = 0.0;
        #pragma unroll
        for (int k = 0; k < 8; k++) s += (double)red[k];
        d_parts[blockIdx.x] = s;
    }
}

// ---------------- deterministic cost finalize ----------------
__global__ void k_costfin(float* __restrict__ costslot) {
    __shared__ double sh[256];
    int t = threadIdx.x;
    double s = 0.0;
    for (int k = 0; k < 64; k++) s += d_parts[t * 64 + k];
    sh[t] = s;
    __syncthreads();
    if (t == 0) {
        double tot = 0.0;
        for (int k = 0; k < 256; k++) tot += sh[k];
        costslot[0] = (float)tot;
    }
}

// ---------------- launch ----------------
extern "C" void kernel_launch(void* const* d_in, const int* in_sizes, int n_in,
                              void* d_out, int out_size) {
    const float* x = (const float*)d_in[0];
    const float* y = (const float*)d_in[1];
    const float* p = (const float*)d_in[2];
    const float* q = (const float*)d_in[3];
    (void)in_sizes; (void)n_in;

    float* out = (float*)d_out;
    float* costslot = nullptr;
    float* Pout = nullptr;
    const long long total = (long long)NN * MM;
    if ((long long)out_size >= total + 1) { costslot = out; Pout = out + 1; }
    else if ((long long)out_size >= total) { Pout = out; }
    else { costslot = out; }

    k_init<<<MM / 256, 256>>>();
    k_norms<<<NN / 8, 256>>>(x, 0);
    k_norms<<<MM / 8, 256>>>(y, 1);
    k_cost<<<dim3(MM / 64, NN / 64), 256>>>(x, y);

    for (int it = 0; it < ITERS; it++) {
        k_row<<<NN / 4, 256>>>(p);
        k_colpart<<<dim3(MM / 256, SLABS), 256>>>();
        k_colfin<<<MM / 256, 256>>>(q);
    }

    k_final<<<(int)(total / 4 / 256), 256>>>(Pout, Pout != nullptr);
    if (costslot) k_costfin<<<1, 256>>>(costslot);
}

// round 2
// speedup vs baseline: 1.0846x; 1.0846x over previous
#include <cuda_runtime.h>
#include <math.h>

#define NN 4096
#define MM 4096
#define DD 64
#define W_EPS 0.1f
#define INV_EPS 10.0f
#define ITERS 10
#define RPS 128                     // rows per slab in column pass
#define SLABS (NN / RPS)            // 32

#define XS_STRIDE 132               // 128 rows + pad, float4-aligned
#define YS_STRIDE 68                // 64 cols + pad, float4-aligned
#define XS_FLOATS (DD * XS_STRIDE)  // 8448
#define YS_FLOATS (DD * YS_STRIDE)  // 4352
#define SMEM_FLOATS (XS_FLOATS + YS_FLOATS)   // 12800 floats = 51200 B

// ------------- static device scratch (no allocations) -------------
__device__ float d_C[(size_t)NN * MM];     // 64 MB
__device__ float d_f[NN];
__device__ float d_g[MM];
__device__ float d_nx[NN];
__device__ float d_ny[MM];
__device__ float d_pm[SLABS * MM];
__device__ float d_ps[SLABS * MM];
__device__ double d_parts[2048];
__device__ unsigned g_barCount;
__device__ volatile unsigned g_barSense;

// ------------- grid-wide barrier (sense-reversing, replay-safe) -------------
__device__ __forceinline__ void grid_barrier(unsigned target, int nb) {
    __syncthreads();
    if (threadIdx.x == 0) {
        __threadfence();
        unsigned v = atomicAdd(&g_barCount, 1u);
        if (v == (unsigned)(nb - 1)) {
            g_barCount = 0u;
            __threadfence();
            g_barSense = target;
        } else {
            while ((int)(g_barSense - target) < 0) __nanosleep(64);
        }
    }
    __syncthreads();
}

extern __shared__ float sh[];

__global__ void __launch_bounds__(256, 4)
k_all(const float* __restrict__ x, const float* __restrict__ y,
      const float* __restrict__ p, const float* __restrict__ q,
      float* __restrict__ Pout, float* __restrict__ costslot, int nb)
{
    const int t = threadIdx.x;
    const int b = blockIdx.x;
    __shared__ float sred[16];
    __shared__ double dred[8];
    unsigned bt = g_barSense;     // same value in all blocks (no arrivals yet)

    // ================= phase 0: norms + g = 0 =================
    {
        int gtid = b * 256 + t;
        if (gtid < MM) d_g[gtid] = 0.0f;
        int lane = t & 31;
        int warpId = gtid >> 5;
        int nwarps = nb * 8;
        for (int row = warpId; row < NN + MM; row += nwarps) {
            const float* src = (row < NN) ? (x + (size_t)row * DD)
                                          : (y + (size_t)(row - NN) * DD);
            float a = src[lane], c = src[lane + 32];
            float s = a * a + c * c;
            #pragma unroll
            for (int o = 16; o; o >>= 1) s += __shfl_xor_sync(0xffffffffu, s, o);
            if (lane == 0) { if (row < NN) d_nx[row] = s; else d_ny[row - NN] = s; }
        }
    }
    grid_barrier(++bt, nb);

    // ================= phase 1: C = nx + ny - 2 x.y (128x64 tiles, 8x4 micro) =================
    {
        float* xs = sh;                 // [DD][XS_STRIDE] transposed
        float* ys = sh + XS_FLOATS;     // [DD][YS_STRIDE] transposed
        const int tx = t & 15, ty = t >> 4;
        const int TILES = (NN / 128) * (MM / 64);   // 2048
        for (int u = b; u < TILES; u += nb) {
            int ur = u & 31;
            int uc = u >> 5;
            int rowBase = ur * 128, colBase = uc * 64;
            __syncthreads();
            #pragma unroll
            for (int k2 = 0; k2 < 8; k2++) {
                int idx = t + 256 * k2;
                int rid = idx >> 4;
                int d4 = (idx & 15) << 2;
                float4 v = *(const float4*)(x + (size_t)(rowBase + rid) * DD + d4);
                xs[(d4 + 0) * XS_STRIDE + rid] = v.x;
                xs[(d4 + 1) * XS_STRIDE + rid] = v.y;
                xs[(d4 + 2) * XS_STRIDE + rid] = v.z;
                xs[(d4 + 3) * XS_STRIDE + rid] = v.w;
            }
            #pragma unroll
            for (int k2 = 0; k2 < 4; k2++) {
                int idx = t + 256 * k2;
                int cid = idx >> 4;
                int d4 = (idx & 15) << 2;
                float4 v = *(const float4*)(y + (size_t)(colBase + cid) * DD + d4);
                ys[(d4 + 0) * YS_STRIDE + cid] = v.x;
                ys[(d4 + 1) * YS_STRIDE + cid] = v.y;
                ys[(d4 + 2) * YS_STRIDE + cid] = v.z;
                ys[(d4 + 3) * YS_STRIDE + cid] = v.w;
            }
            __syncthreads();

            float acc[8][4];
            #pragma unroll
            for (int r = 0; r < 8; r++)
                #pragma unroll
                for (int c = 0; c < 4; c++) acc[r][c] = 0.0f;

            #pragma unroll 8
            for (int d = 0; d < DD; d++) {
                const float* xr = xs + d * XS_STRIDE + (ty << 3);
                float4 a0 = *(const float4*)xr;
                float4 a1 = *(const float4*)(xr + 4);
                float4 bb = *(const float4*)(ys + d * YS_STRIDE + (tx << 2));
                float av[8] = {a0.x, a0.y, a0.z, a0.w, a1.x, a1.y, a1.z, a1.w};
                float bv[4] = {bb.x, bb.y, bb.z, bb.w};
                #pragma unroll
                for (int r = 0; r < 8; r++)
                    #pragma unroll
                    for (int c = 0; c < 4; c++)
                        acc[r][c] = fmaf(av[r], bv[c], acc[r][c]);
            }

            float4 ny4 = *(const float4*)(d_ny + colBase + (tx << 2));
            #pragma unroll
            for (int r = 0; r < 8; r++) {
                int row = rowBase + (ty << 3) + r;
                float nxr = d_nx[row];
                float4 o;
                o.x = nxr + ny4.x - 2.0f * acc[r][0];
                o.y = nxr + ny4.y - 2.0f * acc[r][1];
                o.z = nxr + ny4.z - 2.0f * acc[r][2];
                o.w = nxr + ny4.w - 2.0f * acc[r][3];
                *(float4*)(d_C + (size_t)row * MM + colBase + (tx << 2)) = o;
            }
        }
    }
    grid_barrier(++bt, nb);

    // ================= phase 2: Sinkhorn iterations =================
    for (int it = 0; it < ITERS; it++) {
        // ---- row pass: f_i = eps*(logp_i - LSE_j((g_j - C_ij)/eps)) ----
        {
            float* gs = sh;   // 16 KB staged g
            #pragma unroll
            for (int k2 = 0; k2 < 4; k2++) {
                int j = (t + 256 * k2) * 4;
                *(float4*)(gs + j) = *(const float4*)(d_g + j);
            }
            __syncthreads();
            for (int row = b; row < NN; row += nb) {
                const float* Crow = d_C + (size_t)row * MM;
                float v[16];
                float mx = -1e30f;
                #pragma unroll
                for (int k2 = 0; k2 < 4; k2++) {
                    int j = (t + 256 * k2) * 4;
                    float4 c4 = *(const float4*)(Crow + j);
                    float4 g4 = *(const float4*)(gs + j);
                    v[4 * k2 + 0] = g4.x - c4.x;
                    v[4 * k2 + 1] = g4.y - c4.y;
                    v[4 * k2 + 2] = g4.z - c4.z;
                    v[4 * k2 + 3] = g4.w - c4.w;
                    mx = fmaxf(mx, fmaxf(fmaxf(v[4 * k2], v[4 * k2 + 1]),
                                         fmaxf(v[4 * k2 + 2], v[4 * k2 + 3])));
                }
                // block max
                #pragma unroll
                for (int o = 16; o; o >>= 1) mx = fmaxf(mx, __shfl_xor_sync(0xffffffffu, mx, o));
                if ((t & 31) == 0) sred[t >> 5] = mx;
                __syncthreads();
                if (t == 0) {
                    float m2 = sred[0];
                    #pragma unroll
                    for (int k2 = 1; k2 < 8; k2++) m2 = fmaxf(m2, sred[k2]);
                    sred[8] = m2;
                }
                __syncthreads();
                mx = sred[8];
                float s = 0.0f;
                #pragma unroll
                for (int k2 = 0; k2 < 16; k2++) s += __expf((v[k2] - mx) * INV_EPS);
                #pragma unroll
                for (int o = 16; o; o >>= 1) s += __shfl_xor_sync(0xffffffffu, s, o);
                if ((t & 31) == 0) sred[t >> 5] = s;
                __syncthreads();
                if (t == 0) {
                    float s2 = sred[0];
                    #pragma unroll
                    for (int k2 = 1; k2 < 8; k2++) s2 += sred[k2];
                    d_f[row] = W_EPS * __logf(p[row]) - mx - W_EPS * __logf(s2);
                }
                __syncthreads();
            }
        }
        grid_barrier(++bt, nb);

        // ---- column partials: online LSE over 128-row slabs ----
        {
            const int UNITS = (MM / 256) * SLABS;   // 512
            for (int u = b; u < UNITS; u += nb) {
                int cchunk = u & 15;
                int slab = u >> 4;
                __syncthreads();
                if (t < RPS) sh[t] = d_f[slab * RPS + t];
                __syncthreads();
                int col = cchunk * 256 + t;
                const float* Cp = d_C + (size_t)slab * RPS * MM + col;
                float m = sh[0] - Cp[0];
                float s = 1.0f;
                #pragma unroll 4
                for (int r = 1; r < RPS; r++) {
                    float vv = sh[r] - Cp[(size_t)r * MM];
                    if (vv <= m) {
                        s += __expf((vv - m) * INV_EPS);
                    } else {
                        s = s * __expf((m - vv) * INV_EPS) + 1.0f;
                        m = vv;
                    }
                }
                d_pm[slab * MM + col] = m;
                d_ps[slab * MM + col] = s;
            }
        }
        grid_barrier(++bt, nb);

        // ---- column finalize: g_j ----
        {
            int gtid = b * 256 + t;
            for (int j = gtid; j < MM; j += nb * 256) {
                float m = d_pm[j], s = d_ps[j];
                #pragma unroll
                for (int k2 = 1; k2 < SLABS; k2++) {
                    float mk = d_pm[k2 * MM + j], sk = d_ps[k2 * MM + j];
                    if (mk <= m) {
                        s += sk * __expf((mk - m) * INV_EPS);
                    } else {
                        s = s * __expf((m - mk) * INV_EPS) + sk;
                        m = mk;
                    }
                }
                d_g[j] = W_EPS * __logf(q[j]) - m - W_EPS * __logf(s);
            }
        }
        grid_barrier(++bt, nb);
    }

    // ================= phase 3: P = exp(S), cost partials =================
    {
        double csum = 0.0;
        const int gsz = nb * 256;
        const int gtid = b * 256 + t;
        const int NV4 = (NN * MM) / 4;
        for (int v4 = gtid; v4 < NV4; v4 += gsz) {
            int base = v4 * 4;
            int i = base >> 12;
            int j = base & (MM - 1);
            float4 c4 = *(const float4*)(d_C + (size_t)base);
            float fi = d_f[i];
            float4 g4 = *(const float4*)(d_g + j);
            float p0 = __expf((fi + g4.x - c4.x) * INV_EPS);
            float p1 = __expf((fi + g4.y - c4.y) * INV_EPS);
            float p2 = __expf((fi + g4.z - c4.z) * INV_EPS);
            float p3 = __expf((fi + g4.w - c4.w) * INV_EPS);
            if (Pout) {   // Pout may be out+1: only 4B-aligned -> scalar stores
                Pout[base + 0] = p0; Pout[base + 1] = p1;
                Pout[base + 2] = p2; Pout[base + 3] = p3;
            }
            csum += (double)(p0 * c4.x + p1 * c4.y + p2 * c4.z + p3 * c4.w);
        }
        // deterministic block reduce
        int lane = t & 31;
        #pragma unroll
        for (int o = 16; o; o >>= 1) csum += __shfl_xor_sync(0xffffffffu, csum, o);
        if (lane == 0) dred[t >> 5] = csum;
        __syncthreads();
        if (t == 0) {
            double sb = 0.0;
            #pragma unroll
            for (int k2 = 0; k2 < 8; k2++) sb += dred[k2];
            d_parts[b] = sb;
        }
    }
    grid_barrier(++bt, nb);

    if (b == 0 && costslot) {
        // deterministic two-level final reduce in block 0
        __shared__ double fin[256];
        double s = 0.0;
        for (int k2 = t; k2 < nb; k2 += 256) s += d_parts[k2];   // fixed order per thread
        fin[t] = s;
        __syncthreads();
        if (t == 0) {
            double tot = 0.0;
            for (int k2 = 0; k2 < 256; k2++) tot += fin[k2];
            costslot[0] = (float)tot;
        }
    }
}

// ================= host launch =================
extern "C" void kernel_launch(void* const* d_in, const int* in_sizes, int n_in,
                              void* d_out, int out_size) {
    const float* x = (const float*)d_in[0];
    const float* y = (const float*)d_in[1];
    const float* p = (const float*)d_in[2];
    const float* q = (const float*)d_in[3];
    (void)in_sizes; (void)n_in;

    float* out = (float*)d_out;
    float* costslot = nullptr;
    float* Pout = nullptr;
    const long long total = (long long)NN * MM;
    if ((long long)out_size >= total + 1) { costslot = out; Pout = out + 1; }
    else if ((long long)out_size >= total) { Pout = out; }
    else { costslot = out; }

    int dev = 0;
    cudaGetDevice(&dev);
    cudaDeviceProp prop;
    cudaGetDeviceProperties(&prop, dev);

    size_t shbytes = SMEM_FLOATS * sizeof(float);   // 51200 B
    cudaFuncSetAttribute(k_all, cudaFuncAttributeMaxDynamicSharedMemorySize, (int)shbytes);
    int occ = 0;
    cudaOccupancyMaxActiveBlocksPerMultiprocessor(&occ, k_all, 256, shbytes);
    if (occ < 1) occ = 1;
    long long nb = (long long)prop.multiProcessorCount * occ;
    if (nb > 2048) nb = 2048;

    k_all<<<(int)nb, 256, shbytes>>>(x, y, p, q, Pout, costslot, (int)nb);
}

// round 5
// speedup vs baseline: 1.4917x; 1.3753x over previous
#include <cuda_runtime.h>
#include <math.h>

#define NN 4096
#define MM 4096
#define DD 64
#define W_EPS 0.1f
#define INV_EPS 10.0f
#define ITERS 10
#define RPS 128
#define SLABS (NN / RPS)            // 32

#define XS_STRIDE 132
#define YS_STRIDE 68
#define XS_FLOATS (DD * XS_STRIDE)
#define YS_FLOATS (DD * YS_STRIDE)
#define SMEM_FLOATS (XS_FLOATS + YS_FLOATS)   // 51200 B

// ------------- static device scratch -------------
__device__ float d_C[(size_t)NN * MM];
__device__ float d_f[NN];
__device__ float d_g[MM];
__device__ float d_nx[NN];
__device__ float d_ny[MM];
__device__ float d_pm[SLABS * MM];
__device__ float d_ps[SLABS * MM];
__device__ double d_parts[2048];

// ------------- online-LSE helpers (m raw units, s = sum exp((v-m)/eps)) -------------
__device__ __forceinline__ void lse_merge(float& m1, float& s1, float m2, float s2) {
    float d = (m2 - m1) * INV_EPS;
    float e = __expf(-fabsf(d));
    if (d > 0.0f) { s1 = fmaf(s1, e, s2); m1 = m2; }
    else          { s1 = fmaf(s2, e, s1); }
}
__device__ __forceinline__ void lse_upd1(float& m, float& s, float v) {
    float d = (v - m) * INV_EPS;
    float e = __expf(-fabsf(d));
    bool up = d > 0.0f;
    s = up ? fmaf(s, e, 1.0f) : (s + e);
    m = up ? v : m;
}
__device__ __forceinline__ float4 f4sub(float4 a, float4 b) {
    return make_float4(a.x - b.x, a.y - b.y, a.z - b.z, a.w - b.w);
}
__device__ __forceinline__ float f4max(float4 a) {
    return fmaxf(fmaxf(a.x, a.y), fmaxf(a.z, a.w));
}
__device__ __forceinline__ float f4expsum(float4 a, float mn) {
    return __expf((a.x - mn) * INV_EPS) + __expf((a.y - mn) * INV_EPS)
         + __expf((a.z - mn) * INV_EPS) + __expf((a.w - mn) * INV_EPS);
}

// ================= prep: norms + g = 0 =================
__global__ void k_prep(const float* __restrict__ x, const float* __restrict__ y) {
    int gtid = blockIdx.x * 256 + threadIdx.x;
    if (gtid < MM) d_g[gtid] = 0.0f;
    int lane = threadIdx.x & 31;
    int row = gtid >> 5;                       // 1024 blocks * 8 warps = 8192 rows
    const float* src = (row < NN) ? (x + (size_t)row * DD)
                                  : (y + (size_t)(row - NN) * DD);
    float a = src[lane], c = src[lane + 32];
    float s = a * a + c * c;
    #pragma unroll
    for (int o = 16; o; o >>= 1) s += __shfl_xor_sync(0xffffffffu, s, o);
    if (lane == 0) { if (row < NN) d_nx[row] = s; else d_ny[row - NN] = s; }
}

// ================= cost: C = nx + ny - 2 x.y (128x64 tile, 8x4 micro) =================
extern __shared__ float sh[];
__global__ void __launch_bounds__(256)
k_cost(const float* __restrict__ x, const float* __restrict__ y) {
    float* xs = sh;
    float* ys = sh + XS_FLOATS;
    const int t = threadIdx.x;
    const int tx = t & 15, ty = t >> 4;
    int rowBase = blockIdx.y * 128, colBase = blockIdx.x * 64;

    #pragma unroll
    for (int k2 = 0; k2 < 8; k2++) {
        int idx = t + 256 * k2;
        int rid = idx >> 4;
        int d4 = (idx & 15) << 2;
        float4 v = *(const float4*)(x + (size_t)(rowBase + rid) * DD + d4);
        xs[(d4 + 0) * XS_STRIDE + rid] = v.x;
        xs[(d4 + 1) * XS_STRIDE + rid] = v.y;
        xs[(d4 + 2) * XS_STRIDE + rid] = v.z;
        xs[(d4 + 3) * XS_STRIDE + rid] = v.w;
    }
    #pragma unroll
    for (int k2 = 0; k2 < 4; k2++) {
        int idx = t + 256 * k2;
        int cid = idx >> 4;
        int d4 = (idx & 15) << 2;
        float4 v = *(const float4*)(y + (size_t)(colBase + cid) * DD + d4);
        ys[(d4 + 0) * YS_STRIDE + cid] = v.x;
        ys[(d4 + 1) * YS_STRIDE + cid] = v.y;
        ys[(d4 + 2) * YS_STRIDE + cid] = v.z;
        ys[(d4 + 3) * YS_STRIDE + cid] = v.w;
    }
    __syncthreads();

    float acc[8][4];
    #pragma unroll
    for (int r = 0; r < 8; r++)
        #pragma unroll
        for (int c = 0; c < 4; c++) acc[r][c] = 0.0f;

    #pragma unroll 8
    for (int d = 0; d < DD; d++) {
        const float* xr = xs + d * XS_STRIDE + (ty << 3);
        float4 a0 = *(const float4*)xr;
        float4 a1 = *(const float4*)(xr + 4);
        float4 bb = *(const float4*)(ys + d * YS_STRIDE + (tx << 2));
        float av[8] = {a0.x, a0.y, a0.z, a0.w, a1.x, a1.y, a1.z, a1.w};
        float bv[4] = {bb.x, bb.y, bb.z, bb.w};
        #pragma unroll
        for (int r = 0; r < 8; r++)
            #pragma unroll
            for (int c = 0; c < 4; c++)
                acc[r][c] = fmaf(av[r], bv[c], acc[r][c]);
    }

    float4 ny4 = *(const float4*)(d_ny + colBase + (tx << 2));
    #pragma unroll
    for (int r = 0; r < 8; r++) {
        int row = rowBase + (ty << 3) + r;
        float nxr = d_nx[row];
        float4 o;
        o.x = nxr + ny4.x - 2.0f * acc[r][0];
        o.y = nxr + ny4.y - 2.0f * acc[r][1];
        o.z = nxr + ny4.z - 2.0f * acc[r][2];
        o.w = nxr + ny4.w - 2.0f * acc[r][3];
        *(float4*)(d_C + (size_t)row * MM + colBase + (tx << 2)) = o;
    }
}

// ================= row pass: 2 rows per block, register-resident exact LSE =================
__global__ void __launch_bounds__(256)
k_row(const float* __restrict__ p) {
    __shared__ float s_pm[16], s_ps[16];
    const int t = threadIdx.x;
    const int lane = t & 31;
    const int warp = t >> 5;
    const int r0 = blockIdx.x * 2;
    const float* C0 = d_C + (size_t)r0 * MM;
    const float* C1 = C0 + MM;

    float4 v0[4], v1[4];
    #pragma unroll
    for (int w = 0; w < 4; w++) {
        int j = (t + 256 * w) * 4;
        float4 g4 = *(const float4*)(d_g + j);
        float4 c0 = *(const float4*)(C0 + j);
        float4 c1 = *(const float4*)(C1 + j);
        v0[w] = f4sub(g4, c0);
        v1[w] = f4sub(g4, c1);
    }
    float m0 = fmaxf(fmaxf(f4max(v0[0]), f4max(v0[1])), fmaxf(f4max(v0[2]), f4max(v0[3])));
    float m1 = fmaxf(fmaxf(f4max(v1[0]), f4max(v1[1])), fmaxf(f4max(v1[2]), f4max(v1[3])));
    float s0 = f4expsum(v0[0], m0) + f4expsum(v0[1], m0) + f4expsum(v0[2], m0) + f4expsum(v0[3], m0);
    float s1 = f4expsum(v1[0], m1) + f4expsum(v1[1], m1) + f4expsum(v1[2], m1) + f4expsum(v1[3], m1);

    #pragma unroll
    for (int o = 16; o; o >>= 1) {
        float mo = __shfl_down_sync(0xffffffffu, m0, o);
        float so = __shfl_down_sync(0xffffffffu, s0, o);
        lse_merge(m0, s0, mo, so);
        mo = __shfl_down_sync(0xffffffffu, m1, o);
        so = __shfl_down_sync(0xffffffffu, s1, o);
        lse_merge(m1, s1, mo, so);
    }
    if (lane == 0) {
        s_pm[warp] = m0;     s_ps[warp] = s0;
        s_pm[8 + warp] = m1; s_ps[8 + warp] = s1;
    }
    __syncthreads();
    if (warp == 0) {
        float mm = s_pm[lane & 15], ss = s_ps[lane & 15];
        #pragma unroll
        for (int o = 4; o; o >>= 1) {
            float mo = __shfl_down_sync(0xffffffffu, mm, o, 8);
            float so = __shfl_down_sync(0xffffffffu, ss, o, 8);
            lse_merge(mm, ss, mo, so);
        }
        if (lane == 0) d_f[r0]     = W_EPS * __logf(p[r0])     - mm - W_EPS * __logf(ss);
        if (lane == 8) d_f[r0 + 1] = W_EPS * __logf(p[r0 + 1]) - mm - W_EPS * __logf(ss);
    }
}

// ================= column partials: warp per (slab, 32-col group), 4 ILP chains =================
__global__ void __launch_bounds__(256)
k_colpart() {
    const int lane = threadIdx.x & 31;
    const int warp = threadIdx.x >> 5;
    const int u = blockIdx.x * 8 + warp;     // 512 blocks * 8 warps = 4096 units
    const int slab = u >> 7;
    const int col = ((u & 127) << 5) + lane;
    const float* Cp = d_C + (size_t)slab * RPS * MM + col;
    const float* fp = d_f + slab * RPS;

    float m0 = -3.4e38f, s0 = 0.0f, m1 = -3.4e38f, s1 = 0.0f;
    float m2 = -3.4e38f, s2 = 0.0f, m3 = -3.4e38f, s3 = 0.0f;
    #pragma unroll 8
    for (int k = 0; k < RPS / 4; k++) {
        int r = k * 4;
        float c0 = Cp[(size_t)(r + 0) * MM];
        float c1 = Cp[(size_t)(r + 1) * MM];
        float c2 = Cp[(size_t)(r + 2) * MM];
        float c3 = Cp[(size_t)(r + 3) * MM];
        lse_upd1(m0, s0, fp[r + 0] - c0);
        lse_upd1(m1, s1, fp[r + 1] - c1);
        lse_upd1(m2, s2, fp[r + 2] - c2);
        lse_upd1(m3, s3, fp[r + 3] - c3);
    }
    lse_merge(m0, s0, m1, s1);
    lse_merge(m2, s2, m3, s3);
    lse_merge(m0, s0, m2, s2);
    d_pm[slab * MM + col] = m0;
    d_ps[slab * MM + col] = s0;
}

// ================= column finalize =================
__global__ void __launch_bounds__(256)
k_colfin(const float* __restrict__ q) {
    int j = blockIdx.x * 256 + threadIdx.x;   // 16 blocks
    float m0 = -3.4e38f, s0 = 0.0f, m1 = -3.4e38f, s1 = 0.0f;
    float m2 = -3.4e38f, s2 = 0.0f, m3 = -3.4e38f, s3 = 0.0f;
    #pragma unroll
    for (int k = 0; k < SLABS / 4; k++) {
        int k4 = k * 4;
        lse_merge(m0, s0, d_pm[(k4 + 0) * MM + j], d_ps[(k4 + 0) * MM + j]);
        lse_merge(m1, s1, d_pm[(k4 + 1) * MM + j], d_ps[(k4 + 1) * MM + j]);
        lse_merge(m2, s2, d_pm[(k4 + 2) * MM + j], d_ps[(k4 + 2) * MM + j]);
        lse_merge(m3, s3, d_pm[(k4 + 3) * MM + j], d_ps[(k4 + 3) * MM + j]);
    }
    lse_merge(m0, s0, m1, s1);
    lse_merge(m2, s2, m3, s3);
    lse_merge(m0, s0, m2, s2);
    d_g[j] = W_EPS * __logf(q[j]) - m0 - W_EPS * __logf(s0);
}

// ================= final: P = exp(S), cost partials =================
__global__ void __launch_bounds__(256)
k_final(float* __restrict__ Pout, int writeP) {
    __shared__ double dred[8];
    const int gsz = 2048 * 256;
    const int gtid = blockIdx.x * 256 + threadIdx.x;
    const int NV4 = (NN * MM) / 4;
    double csum = 0.0;
    #pragma unroll 4
    for (int v4 = gtid; v4 < NV4; v4 += gsz) {
        int base = v4 * 4;
        int i = base >> 12;
        int j = base & (MM - 1);
        float4 c4 = *(const float4*)(d_C + (size_t)base);
        float fi = d_f[i];
        float4 g4 = *(const float4*)(d_g + j);
        float p0 = __expf((fi + g4.x - c4.x) * INV_EPS);
        float p1 = __expf((fi + g4.y - c4.y) * INV_EPS);
        float p2 = __expf((fi + g4.z - c4.z) * INV_EPS);
        float p3 = __expf((fi + g4.w - c4.w) * INV_EPS);
        if (writeP) {
            Pout[base + 0] = p0; Pout[base + 1] = p1;
            Pout[base + 2] = p2; Pout[base + 3] = p3;
        }
        csum += (double)(p0 * c4.x + p1 * c4.y + p2 * c4.z + p3 * c4.w);
    }
    #pragma unroll
    for (int o = 16; o; o >>= 1) csum += __shfl_xor_sync(0xffffffffu, csum, o);
    if ((threadIdx.x & 31) == 0) dred[threadIdx.x >> 5] = csum;
    __syncthreads();
    if (threadIdx.x == 0) {
        double sb = 0.0;
        #pragma unroll
        for (int k2 = 0; k2 < 8; k2++) sb += dred[k2];
        d_parts[blockIdx.x] = sb;
    }
}

__global__ void k_costfin(float* __restrict__ costslot) {
    __shared__ double fin[256];
    int t = threadIdx.x;
    double s = 0.0;
    for (int k2 = t; k2 < 2048; k2 += 256) s += d_parts[k2];
    fin[t] = s;
    __syncthreads();
    if (t == 0) {
        double tot = 0.0;
        for (int k2 = 0; k2 < 256; k2++) tot += fin[k2];
        costslot[0] = (float)tot;
    }
}

// ================= host launch =================
extern "C" void kernel_launch(void* const* d_in, const int* in_sizes, int n_in,
                              void* d_out, int out_size) {
    const float* x = (const float*)d_in[0];
    const float* y = (const float*)d_in[1];
    const float* p = (const float*)d_in[2];
    const float* q = (const float*)d_in[3];
    (void)in_sizes; (void)n_in;

    float* out = (float*)d_out;
    float* costslot = nullptr;
    float* Pout = nullptr;
    const long long total = (long long)NN * MM;
    if ((long long)out_size >= total + 1) { costslot = out; Pout = out + 1; }
    else if ((long long)out_size >= total) { Pout = out; }
    else { costslot = out; }

    size_t shbytes = SMEM_FLOATS * sizeof(float);
    static int shset = 0;
    if (!shset) {
        cudaFuncSetAttribute(k_cost, cudaFuncAttributeMaxDynamicSharedMemorySize, (int)shbytes);
        shset = 1;
    }

    k_prep<<<1024, 256>>>(x, y);
    k_cost<<<dim3(MM / 64, NN / 128), 256, shbytes>>>(x, y);

    for (int it = 0; it < ITERS; it++) {
        k_row<<<NN / 2, 256>>>(p);
        k_colpart<<<512, 256>>>();
        k_colfin<<<16, 256>>>(q);
    }

    k_final<<<2048, 256>>>(Pout, Pout != nullptr);
    if (costslot) k_costfin<<<1, 256>>>(costslot);
}